// round 1
// baseline (speedup 1.0000x reference)
#include <cuda_runtime.h>
#include <math.h>
#include <stdint.h>

#define SEQ   2048
#define DIM   4096
#define NH    32
#define NKV   8
#define HD    128
#define KVD   1024   // NKV*HD
#define SCALE 0.08838834764831845f

// ---------------- scratch (static device globals; no allocation allowed) ----
__device__ float g_q[SEQ * DIM];
__device__ float g_k[SEQ * KVD];
__device__ float g_v[SEQ * KVD];
__device__ float g_att[SEQ * DIM];

// ---------------- GEMM: C[M,N] = A[M,K] @ B[K,N], all dims % 128 == 0 -------
// 128x128 block tile, 256 threads, 8x8 per thread (2x2 of 4x4, 64-split).
__global__ __launch_bounds__(256) void gemm_kernel(
    const float* __restrict__ A, const float* __restrict__ B,
    float* __restrict__ C, int M, int N, int K)
{
    __shared__ float As[8][128];
    __shared__ float Bs[8][128];

    const int t  = threadIdx.x;
    const int tx = t & 15, ty = t >> 4;
    const int m0 = blockIdx.y << 7, n0 = blockIdx.x << 7;

    float acc[2][2][4][4];
#pragma unroll
    for (int a = 0; a < 2; a++)
#pragma unroll
        for (int b = 0; b < 2; b++)
#pragma unroll
            for (int i = 0; i < 4; i++)
#pragma unroll
                for (int j = 0; j < 4; j++) acc[a][b][i][j] = 0.f;

    const int arow = t >> 1, ak = (t & 1) * 4;
    const int brow = t >> 5, bcol = (t & 31) * 4;
    const float* Ap = A + (size_t)(m0 + arow) * K + ak;
    const float* Bp = B + (size_t)brow * N + n0 + bcol;

    for (int k0 = 0; k0 < K; k0 += 8) {
        float4 av = *(const float4*)(Ap + k0);
        float4 bv = *(const float4*)(Bp + (size_t)k0 * N);
        __syncthreads();                 // protect prior-iter shared reads
        As[ak + 0][arow] = av.x;
        As[ak + 1][arow] = av.y;
        As[ak + 2][arow] = av.z;
        As[ak + 3][arow] = av.w;
        *(float4*)&Bs[brow][bcol] = bv;
        __syncthreads();
#pragma unroll
        for (int kk = 0; kk < 8; kk++) {
            float a0[4], a1[4], b0[4], b1[4];
            *(float4*)a0 = *(const float4*)&As[kk][ty * 4];
            *(float4*)a1 = *(const float4*)&As[kk][ty * 4 + 64];
            *(float4*)b0 = *(const float4*)&Bs[kk][tx * 4];
            *(float4*)b1 = *(const float4*)&Bs[kk][tx * 4 + 64];
#pragma unroll
            for (int i = 0; i < 4; i++)
#pragma unroll
                for (int j = 0; j < 4; j++) {
                    acc[0][0][i][j] += a0[i] * b0[j];
                    acc[0][1][i][j] += a0[i] * b1[j];
                    acc[1][0][i][j] += a1[i] * b0[j];
                    acc[1][1][i][j] += a1[i] * b1[j];
                }
        }
    }

#pragma unroll
    for (int ri = 0; ri < 2; ri++)
#pragma unroll
        for (int i = 0; i < 4; i++) {
            int row = m0 + ri * 64 + ty * 4 + i;
#pragma unroll
            for (int ci = 0; ci < 2; ci++) {
                float4 o = make_float4(acc[ri][ci][i][0], acc[ri][ci][i][1],
                                       acc[ri][ci][i][2], acc[ri][ci][i][3]);
                *(float4*)(C + (size_t)row * N + n0 + ci * 64 + tx * 4) = o;
            }
        }
}

// ---------------- RoPE on Q and K (in place) --------------------------------
__global__ void rope_kernel(float* __restrict__ q, float* __restrict__ k,
                            const float* __restrict__ fc,
                            const float* __restrict__ fs)
{
    int idx = blockIdx.x * blockDim.x + threadIdx.x;
    const int qn = SEQ * NH * (HD / 2);
    const int kn = SEQ * NKV * (HD / 2);
    if (idx < qn) {
        int s   = idx / (NH * 64);
        int rem = idx - s * (NH * 64);
        int h = rem >> 6, i = rem & 63;
        float c = fc[s * 64 + i], sn = fs[s * 64 + i];
        float* p = q + (size_t)s * DIM + h * HD + 2 * i;
        float t1 = p[0], t2 = p[1];
        p[0] = t1 * c - t2 * sn;
        p[1] = t1 * sn + t2 * c;
    } else if (idx < qn + kn) {
        int j   = idx - qn;
        int s   = j / (NKV * 64);
        int rem = j - s * (NKV * 64);
        int h = rem >> 6, i = rem & 63;
        float c = fc[s * 64 + i], sn = fs[s * 64 + i];
        float* p = k + (size_t)s * KVD + h * HD + 2 * i;
        float t1 = p[0], t2 = p[1];
        p[0] = t1 * c - t2 * sn;
        p[1] = t1 * sn + t2 * c;
    }
}

// ---------------- flash attention (fp32, online softmax) --------------------
// block = (head, 64-query tile); 256 threads; key tiles of 64.
#define BR  64
#define BC  64
#define QSP 132   // Qs row stride (floats)
#define KTS 68    // Kt row stride
#define VSP 132   // Vs row stride
#define SSP 68    // Ss row stride
// smem floats: Qs 64*132 + Kt 128*68 + Vs 64*132 + Ss 64*68 + 3*64
#define ATTN_SMEM_FLOATS (BR*QSP + HD*KTS + BC*VSP + BR*SSP + 3*BR)
#define ATTN_SMEM_BYTES  (ATTN_SMEM_FLOATS * 4)

__global__ __launch_bounds__(256) void attn_kernel(
    const float* __restrict__ Q, const float* __restrict__ K,
    const float* __restrict__ V, float* __restrict__ O)
{
    extern __shared__ float sm[];
    float* Qs  = sm;
    float* Kt  = Qs + BR * QSP;
    float* Vs  = Kt + HD * KTS;
    float* Ss  = Vs + BC * VSP;
    float* m_s = Ss + BR * SSP;
    float* l_s = m_s + BR;
    float* a_s = l_s + BR;

    const int h   = blockIdx.y;
    const int q0  = blockIdx.x * BR;
    const int kvh = h >> 2;          // REPEATS = 4
    const int t   = threadIdx.x;
    const int tx  = t & 15, ty = t >> 4;

    // load Q tile (pre-scaled)
#pragma unroll
    for (int p = 0; p < (BR * HD) / (256 * 4); p++) {
        int i = (t + p * 256) * 4;
        int r = i >> 7, d = i & 127;
        float4 xq = *(const float4*)(Q + (size_t)(q0 + r) * DIM + h * HD + d);
        float* dst = Qs + r * QSP + d;
        dst[0] = xq.x * SCALE; dst[1] = xq.y * SCALE;
        dst[2] = xq.z * SCALE; dst[3] = xq.w * SCALE;
    }
    if (t < BR) { m_s[t] = -INFINITY; l_s[t] = 0.f; }

    float acc[4][8];
#pragma unroll
    for (int i = 0; i < 4; i++)
#pragma unroll
        for (int j = 0; j < 8; j++) acc[i][j] = 0.f;

    for (int k0 = 0; k0 < SEQ; k0 += BC) {
        __syncthreads();   // Q/m/l ready (iter 0); prior PV done (iter >0)

        // load K (transposed + XOR-swizzled) and V tiles
#pragma unroll
        for (int p = 0; p < (BC * HD) / (256 * 4); p++) {
            int i = (t + p * 256) * 4;
            int r = i >> 7, d = i & 127;           // d % 4 == 0
            float4 kv = *(const float4*)(K + (size_t)(k0 + r) * KVD + kvh * HD + d);
            int c = r ^ (d & 60);                  // swizzled column
            Kt[(d + 0) * KTS + c] = kv.x;
            Kt[(d + 1) * KTS + c] = kv.y;
            Kt[(d + 2) * KTS + c] = kv.z;
            Kt[(d + 3) * KTS + c] = kv.w;
            float4 vv = *(const float4*)(V + (size_t)(k0 + r) * KVD + kvh * HD + d);
            *(float4*)(Vs + r * VSP + d) = vv;
        }
        __syncthreads();

        // S = Q K^T  (each thread: 4 rows x 4 cols)
        float s_acc[4][4];
#pragma unroll
        for (int i = 0; i < 4; i++)
#pragma unroll
            for (int j = 0; j < 4; j++) s_acc[i][j] = 0.f;
#pragma unroll 4
        for (int kk = 0; kk < HD; kk++) {
            float4 kv = *(const float4*)(Kt + kk * KTS + ((tx * 4) ^ (kk & 60)));
            float qv[4];
#pragma unroll
            for (int i = 0; i < 4; i++) qv[i] = Qs[(ty * 4 + i) * QSP + kk];
#pragma unroll
            for (int i = 0; i < 4; i++) {
                s_acc[i][0] += qv[i] * kv.x;
                s_acc[i][1] += qv[i] * kv.y;
                s_acc[i][2] += qv[i] * kv.z;
                s_acc[i][3] += qv[i] * kv.w;
            }
        }
#pragma unroll
        for (int i = 0; i < 4; i++) {
            float4 sv = make_float4(s_acc[i][0], s_acc[i][1], s_acc[i][2], s_acc[i][3]);
            *(float4*)(Ss + (ty * 4 + i) * SSP + tx * 4) = sv;
        }
        __syncthreads();

        // online softmax (one thread per query row)
        if (t < BR) {
            float mo = m_s[t];
            float mx = mo;
            float* row = Ss + t * SSP;
#pragma unroll 8
            for (int j = 0; j < BC; j++) mx = fmaxf(mx, row[j]);
            float sum = 0.f;
#pragma unroll 8
            for (int j = 0; j < BC; j++) {
                float e = __expf(row[j] - mx);
                row[j] = e;
                sum += e;
            }
            float alpha = __expf(mo - mx);   // == 0 on first tile (mo = -inf)
            a_s[t] = alpha;
            m_s[t] = mx;
            l_s[t] = l_s[t] * alpha + sum;
        }
        __syncthreads();

        // rescale O, then O += P @ V  (each thread: 4 rows x 8 cols)
#pragma unroll
        for (int i = 0; i < 4; i++) {
            float al = a_s[ty * 4 + i];
#pragma unroll
            for (int j = 0; j < 8; j++) acc[i][j] *= al;
        }
#pragma unroll 2
        for (int kk = 0; kk < BC; kk++) {
            float4 v0 = *(const float4*)(Vs + kk * VSP + tx * 8);
            float4 v1 = *(const float4*)(Vs + kk * VSP + tx * 8 + 4);
#pragma unroll
            for (int i = 0; i < 4; i++) {
                float p = Ss[(ty * 4 + i) * SSP + kk];
                acc[i][0] += p * v0.x; acc[i][1] += p * v0.y;
                acc[i][2] += p * v0.z; acc[i][3] += p * v0.w;
                acc[i][4] += p * v1.x; acc[i][5] += p * v1.y;
                acc[i][6] += p * v1.z; acc[i][7] += p * v1.w;
            }
        }
    }

    // finalize: O /= l, store
#pragma unroll
    for (int i = 0; i < 4; i++) {
        int r = ty * 4 + i;
        float inv = 1.0f / l_s[r];
        float* op = O + (size_t)(q0 + r) * DIM + h * HD + tx * 8;
        float4 o0 = make_float4(acc[i][0] * inv, acc[i][1] * inv,
                                acc[i][2] * inv, acc[i][3] * inv);
        float4 o1 = make_float4(acc[i][4] * inv, acc[i][5] * inv,
                                acc[i][6] * inv, acc[i][7] * inv);
        *(float4*)op       = o0;
        *(float4*)(op + 4) = o1;
    }
}

// ---------------- launch ----------------------------------------------------
extern "C" void kernel_launch(void* const* d_in, const int* in_sizes, int n_in,
                              void* d_out, int out_size)
{
    const float* x  = (const float*)d_in[0];
    const float* fc = (const float*)d_in[1];
    const float* fs = (const float*)d_in[2];
    const float* wq = (const float*)d_in[3];
    const float* wk = (const float*)d_in[4];
    const float* wv = (const float*)d_in[5];
    const float* wo = (const float*)d_in[6];
    float* out = (float*)d_out;

    float *q, *k, *v, *att;
    cudaGetSymbolAddress((void**)&q,   g_q);
    cudaGetSymbolAddress((void**)&k,   g_k);
    cudaGetSymbolAddress((void**)&v,   g_v);
    cudaGetSymbolAddress((void**)&att, g_att);

    cudaFuncSetAttribute(attn_kernel,
                         cudaFuncAttributeMaxDynamicSharedMemorySize,
                         ATTN_SMEM_BYTES);

    dim3 blk(256);
    gemm_kernel<<<dim3(DIM / 128, SEQ / 128), blk>>>(x, wq, q, SEQ, DIM, DIM);
    gemm_kernel<<<dim3(KVD / 128, SEQ / 128), blk>>>(x, wk, k, SEQ, KVD, DIM);
    gemm_kernel<<<dim3(KVD / 128, SEQ / 128), blk>>>(x, wv, v, SEQ, KVD, DIM);

    int nrope = SEQ * (NH + NKV) * (HD / 2);
    rope_kernel<<<(nrope + 255) / 256, 256>>>(q, k, fc, fs);

    attn_kernel<<<dim3(SEQ / BR, NH), blk, ATTN_SMEM_BYTES>>>(q, k, v, att);

    gemm_kernel<<<dim3(DIM / 128, SEQ / 128), blk>>>(att, wo, out, SEQ, DIM, DIM);
}

// round 3
// speedup vs baseline: 1.6309x; 1.6309x over previous
#include <cuda_runtime.h>
#include <cuda_bf16.h>
#include <math.h>
#include <stdint.h>

#define SEQ   2048
#define DIM   4096
#define NH    32
#define NKV   8
#define HD    128
#define KVD   1024
#define SCALE 0.08838834764831845f

// ---------------- scratch ----------------------------------------------------
__device__ float g_q[SEQ * DIM];
__device__ float g_k[SEQ * KVD];
__device__ float g_v[SEQ * KVD];
__device__ float g_att[SEQ * DIM];

__device__ __nv_bfloat16 g_x_hi[SEQ * DIM],  g_x_lo[SEQ * DIM];
__device__ __nv_bfloat16 g_att_hi[SEQ * DIM], g_att_lo[SEQ * DIM];
__device__ __nv_bfloat16 g_wqT_hi[DIM * DIM], g_wqT_lo[DIM * DIM];
__device__ __nv_bfloat16 g_wkT_hi[KVD * DIM], g_wkT_lo[KVD * DIM];
__device__ __nv_bfloat16 g_wvT_hi[KVD * DIM], g_wvT_lo[KVD * DIM];
__device__ __nv_bfloat16 g_woT_hi[DIM * DIM], g_woT_lo[DIM * DIM];

// ---------------- PTX helpers (baseline PTX only: no tcgen05!) ----------------
__device__ __forceinline__ uint32_t smem_u32(const void* p) {
    uint32_t a;
    asm("{ .reg .u64 t; cvta.to.shared.u64 t, %1; cvt.u32.u64 %0, t; }"
        : "=r"(a) : "l"(p));
    return a;
}
#define CP_ASYNC16(dst, src) \
    asm volatile("cp.async.cg.shared.global [%0], [%1], 16;" :: "r"(dst), "l"(src) : "memory")
#define CP_COMMIT()  asm volatile("cp.async.commit_group;" ::: "memory")
#define CP_WAIT(n)   asm volatile("cp.async.wait_group %0;" :: "n"(n) : "memory")

#define LDSM_X4(r, addr)                                                      \
    asm volatile("ldmatrix.sync.aligned.m8n8.x4.shared.b16 {%0,%1,%2,%3}, [%4];" \
        : "=r"((r)[0]), "=r"((r)[1]), "=r"((r)[2]), "=r"((r)[3]) : "r"(addr))

#define MMA_BF16(d, a, b0, b1)                                                \
    asm volatile("mma.sync.aligned.m16n8k16.row.col.f32.bf16.bf16.f32 "       \
        "{%0,%1,%2,%3}, {%4,%5,%6,%7}, {%8,%9}, {%0,%1,%2,%3};"               \
        : "+f"((d)[0]), "+f"((d)[1]), "+f"((d)[2]), "+f"((d)[3])              \
        : "r"((a)[0]), "r"((a)[1]), "r"((a)[2]), "r"((a)[3]), "r"(b0), "r"(b1))

// ---------------- elementwise split fp32 -> bf16 hi/lo ------------------------
__global__ void split_kernel(const float* __restrict__ in,
                             __nv_bfloat16* __restrict__ hi,
                             __nv_bfloat16* __restrict__ lo, int n4)
{
    int i = blockIdx.x * blockDim.x + threadIdx.x;
    if (i >= n4) return;
    float4 v = ((const float4*)in)[i];
    __nv_bfloat16 h0 = __float2bfloat16(v.x);
    __nv_bfloat16 h1 = __float2bfloat16(v.y);
    __nv_bfloat16 h2 = __float2bfloat16(v.z);
    __nv_bfloat16 h3 = __float2bfloat16(v.w);
    __nv_bfloat16 l0 = __float2bfloat16(v.x - __bfloat162float(h0));
    __nv_bfloat16 l1 = __float2bfloat16(v.y - __bfloat162float(h1));
    __nv_bfloat16 l2 = __float2bfloat16(v.z - __bfloat162float(h2));
    __nv_bfloat16 l3 = __float2bfloat16(v.w - __bfloat162float(h3));
    __nv_bfloat162* hp = (__nv_bfloat162*)hi;
    __nv_bfloat162* lp = (__nv_bfloat162*)lo;
    __nv_bfloat162 a; a.x = h0; a.y = h1; hp[i * 2] = a;
    __nv_bfloat162 b; b.x = h2; b.y = h3; hp[i * 2 + 1] = b;
    __nv_bfloat162 c; c.x = l0; c.y = l1; lp[i * 2] = c;
    __nv_bfloat162 d; d.x = l2; d.y = l3; lp[i * 2 + 1] = d;
}

// ---------------- transpose + split: B[K,N] fp32 -> BT[N,K] bf16 hi/lo --------
__global__ void tsplit_kernel(const float* __restrict__ B,
                              __nv_bfloat16* __restrict__ Th,
                              __nv_bfloat16* __restrict__ Tl, int K, int N)
{
    __shared__ float tile[32][33];
    int n0 = blockIdx.x * 32, k0 = blockIdx.y * 32;
    int tx = threadIdx.x, ty = threadIdx.y;   // 32 x 8
#pragma unroll
    for (int i = 0; i < 32; i += 8)
        tile[ty + i][tx] = B[(size_t)(k0 + ty + i) * N + n0 + tx];
    __syncthreads();
#pragma unroll
    for (int i = 0; i < 32; i += 8) {
        float v = tile[tx][ty + i];
        __nv_bfloat16 h = __float2bfloat16(v);
        __nv_bfloat16 l = __float2bfloat16(v - __bfloat162float(h));
        size_t o = (size_t)(n0 + ty + i) * K + k0 + tx;
        Th[o] = h;
        Tl[o] = l;
    }
}

// ---------------- mma.sync GEMM: C[M,N] = (Ah+Al)[M,K] @ (Bh+Bl)[N,K]^T --------
// 128x128 CTA tile, BK=32, bf16x3 split, fp32 accumulate in registers.
// 8 warps: wm = w&1 (64 rows each), wn = w>>1 (32 cols each).
#define BK    32
#define TSTR  40                       // smem row stride (elements)
#define TILE_E (128 * TSTR)            // elements per tile
#define GEMM_SMEM (2 * 4 * TILE_E * 2) // 2 buffers x 4 tiles x bytes = 81920

__global__ __launch_bounds__(256, 2) void gemm_mma(
    const __nv_bfloat16* __restrict__ Ah, const __nv_bfloat16* __restrict__ Al,
    const __nv_bfloat16* __restrict__ Bh, const __nv_bfloat16* __restrict__ Bl,
    float* __restrict__ C, int M, int N, int K)
{
    extern __shared__ __nv_bfloat16 smb[];
    const uint32_t sbase = smem_u32(smb);
    const int t    = threadIdx.x;
    const int lane = t & 31;
    const int w    = t >> 5;
    const int wm   = w & 1, wn = w >> 1;
    const int m0   = blockIdx.y << 7, n0 = blockIdx.x << 7;

    const __nv_bfloat16* srcs[4] = {
        Ah + (size_t)m0 * K, Al + (size_t)m0 * K,
        Bh + (size_t)n0 * K, Bl + (size_t)n0 * K };

    const int lr = t >> 2, lc = (t & 3) * 8;   // cp.async: row, col-chunk

    float acc[4][4][4];
#pragma unroll
    for (int a = 0; a < 4; a++)
#pragma unroll
        for (int b = 0; b < 4; b++)
#pragma unroll
            for (int c = 0; c < 4; c++) acc[a][b][c] = 0.f;

    // prologue: buffer 0
#pragma unroll
    for (int tile = 0; tile < 4; tile++) {
        const __nv_bfloat16* s = srcs[tile];
        uint32_t d = sbase + (uint32_t)(tile * TILE_E) * 2;
        CP_ASYNC16(d + (lr * TSTR + lc) * 2,        s + (size_t)lr * K + lc);
        CP_ASYNC16(d + ((lr + 64) * TSTR + lc) * 2, s + (size_t)(lr + 64) * K + lc);
    }
    CP_COMMIT();

    const int niter = K / BK;
    for (int i = 0; i < niter; i++) {
        const int b = i & 1;
        if (i + 1 < niter) {
            const int nb = b ^ 1;
            const size_t koff = (size_t)(i + 1) * BK;
#pragma unroll
            for (int tile = 0; tile < 4; tile++) {
                const __nv_bfloat16* s = srcs[tile] + koff;
                uint32_t d = sbase + (uint32_t)((nb * 4 + tile) * TILE_E) * 2;
                CP_ASYNC16(d + (lr * TSTR + lc) * 2,        s + (size_t)lr * K + lc);
                CP_ASYNC16(d + ((lr + 64) * TSTR + lc) * 2, s + (size_t)(lr + 64) * K + lc);
            }
            CP_COMMIT();
            CP_WAIT(1);
        } else {
            CP_WAIT(0);
        }
        __syncthreads();

        const uint32_t Ah_s = sbase + (uint32_t)((b * 4 + 0) * TILE_E) * 2;
        const uint32_t Al_s = sbase + (uint32_t)((b * 4 + 1) * TILE_E) * 2;
        const uint32_t Bh_s = sbase + (uint32_t)((b * 4 + 2) * TILE_E) * 2;
        const uint32_t Bl_s = sbase + (uint32_t)((b * 4 + 3) * TILE_E) * 2;

#pragma unroll
        for (int ks = 0; ks < 2; ks++) {
            const int koff = ks * 16 + (lane >> 4) * 8;
            const int arow = wm * 64 + (lane & 15);
            const int brow = wn * 32 + (lane & 15);

            uint32_t ah[4][4], al[4][4], bh[2][4], bl[2][4];
#pragma unroll
            for (int mt = 0; mt < 4; mt++) {
                uint32_t off = (uint32_t)((arow + mt * 16) * TSTR + koff) * 2;
                LDSM_X4(ah[mt], Ah_s + off);
                LDSM_X4(al[mt], Al_s + off);
            }
#pragma unroll
            for (int np = 0; np < 2; np++) {
                uint32_t off = (uint32_t)((brow + np * 16) * TSTR + koff) * 2;
                LDSM_X4(bh[np], Bh_s + off);
                LDSM_X4(bl[np], Bl_s + off);
            }
#pragma unroll
            for (int mt = 0; mt < 4; mt++)
#pragma unroll
                for (int nt = 0; nt < 4; nt++) {
                    const int np = nt >> 1, sel = nt & 1;
                    MMA_BF16(acc[mt][nt], ah[mt], bh[np][sel], bh[np][sel + 2]);
                    MMA_BF16(acc[mt][nt], ah[mt], bl[np][sel], bl[np][sel + 2]);
                    MMA_BF16(acc[mt][nt], al[mt], bh[np][sel], bh[np][sel + 2]);
                }
        }
        __syncthreads();
    }

    // epilogue: m16n8 fragment layout -> gmem
#pragma unroll
    for (int mt = 0; mt < 4; mt++) {
        const int r = m0 + wm * 64 + mt * 16 + (lane >> 2);
#pragma unroll
        for (int nt = 0; nt < 4; nt++) {
            const int c = n0 + wn * 32 + nt * 8 + (lane & 3) * 2;
            *(float2*)(C + (size_t)r * N + c) =
                make_float2(acc[mt][nt][0], acc[mt][nt][1]);
            *(float2*)(C + (size_t)(r + 8) * N + c) =
                make_float2(acc[mt][nt][2], acc[mt][nt][3]);
        }
    }
}

// ---------------- RoPE on Q and K (in place) ---------------------------------
__global__ void rope_kernel(float* __restrict__ q, float* __restrict__ k,
                            const float* __restrict__ fc,
                            const float* __restrict__ fs)
{
    int idx = blockIdx.x * blockDim.x + threadIdx.x;
    const int qn = SEQ * NH * (HD / 2);
    const int kn = SEQ * NKV * (HD / 2);
    if (idx < qn) {
        int s = idx / (NH * 64);
        int rem = idx - s * (NH * 64);
        int h = rem >> 6, i = rem & 63;
        float c = fc[s * 64 + i], sn = fs[s * 64 + i];
        float* p = q + (size_t)s * DIM + h * HD + 2 * i;
        float t1 = p[0], t2 = p[1];
        p[0] = t1 * c - t2 * sn;
        p[1] = t1 * sn + t2 * c;
    } else if (idx < qn + kn) {
        int j = idx - qn;
        int s = j / (NKV * 64);
        int rem = j - s * (NKV * 64);
        int h = rem >> 6, i = rem & 63;
        float c = fc[s * 64 + i], sn = fs[s * 64 + i];
        float* p = k + (size_t)s * KVD + h * HD + 2 * i;
        float t1 = p[0], t2 = p[1];
        p[0] = t1 * c - t2 * sn;
        p[1] = t1 * sn + t2 * c;
    }
}

// ---------------- flash attention (fp32, online softmax) ----------------------
#define BR  64
#define BC  64
#define QSP 132
#define KTS 68
#define VSP 132
#define SSP 68
#define ATTN_SMEM_FLOATS (BR*QSP + HD*KTS + BC*VSP + BR*SSP + 3*BR)
#define ATTN_SMEM_BYTES  (ATTN_SMEM_FLOATS * 4)

__global__ __launch_bounds__(256) void attn_kernel(
    const float* __restrict__ Q, const float* __restrict__ K,
    const float* __restrict__ V, float* __restrict__ O)
{
    extern __shared__ float sm[];
    float* Qs  = sm;
    float* Kt  = Qs + BR * QSP;
    float* Vs  = Kt + HD * KTS;
    float* Ss  = Vs + BC * VSP;
    float* m_s = Ss + BR * SSP;
    float* l_s = m_s + BR;
    float* a_s = l_s + BR;

    const int h   = blockIdx.y;
    const int q0  = blockIdx.x * BR;
    const int kvh = h >> 2;
    const int t   = threadIdx.x;
    const int tx  = t & 15, ty = t >> 4;

#pragma unroll
    for (int p = 0; p < (BR * HD) / (256 * 4); p++) {
        int i = (t + p * 256) * 4;
        int r = i >> 7, d = i & 127;
        float4 xq = *(const float4*)(Q + (size_t)(q0 + r) * DIM + h * HD + d);
        float* dst = Qs + r * QSP + d;
        dst[0] = xq.x * SCALE; dst[1] = xq.y * SCALE;
        dst[2] = xq.z * SCALE; dst[3] = xq.w * SCALE;
    }
    if (t < BR) { m_s[t] = -INFINITY; l_s[t] = 0.f; }

    float acc[4][8];
#pragma unroll
    for (int i = 0; i < 4; i++)
#pragma unroll
        for (int j = 0; j < 8; j++) acc[i][j] = 0.f;

    for (int k0 = 0; k0 < SEQ; k0 += BC) {
        __syncthreads();
#pragma unroll
        for (int p = 0; p < (BC * HD) / (256 * 4); p++) {
            int i = (t + p * 256) * 4;
            int r = i >> 7, d = i & 127;
            float4 kv = *(const float4*)(K + (size_t)(k0 + r) * KVD + kvh * HD + d);
            int c = r ^ (d & 60);
            Kt[(d + 0) * KTS + c] = kv.x;
            Kt[(d + 1) * KTS + c] = kv.y;
            Kt[(d + 2) * KTS + c] = kv.z;
            Kt[(d + 3) * KTS + c] = kv.w;
            float4 vv = *(const float4*)(V + (size_t)(k0 + r) * KVD + kvh * HD + d);
            *(float4*)(Vs + r * VSP + d) = vv;
        }
        __syncthreads();

        float s_acc[4][4];
#pragma unroll
        for (int i = 0; i < 4; i++)
#pragma unroll
            for (int j = 0; j < 4; j++) s_acc[i][j] = 0.f;
#pragma unroll 4
        for (int kk = 0; kk < HD; kk++) {
            float4 kv = *(const float4*)(Kt + kk * KTS + ((tx * 4) ^ (kk & 60)));
            float qv[4];
#pragma unroll
            for (int i = 0; i < 4; i++) qv[i] = Qs[(ty * 4 + i) * QSP + kk];
#pragma unroll
            for (int i = 0; i < 4; i++) {
                s_acc[i][0] += qv[i] * kv.x;
                s_acc[i][1] += qv[i] * kv.y;
                s_acc[i][2] += qv[i] * kv.z;
                s_acc[i][3] += qv[i] * kv.w;
            }
        }
#pragma unroll
        for (int i = 0; i < 4; i++) {
            float4 sv = make_float4(s_acc[i][0], s_acc[i][1], s_acc[i][2], s_acc[i][3]);
            *(float4*)(Ss + (ty * 4 + i) * SSP + tx * 4) = sv;
        }
        __syncthreads();

        if (t < BR) {
            float mo = m_s[t];
            float mx = mo;
            float* row = Ss + t * SSP;
#pragma unroll 8
            for (int j = 0; j < BC; j++) mx = fmaxf(mx, row[j]);
            float sum = 0.f;
#pragma unroll 8
            for (int j = 0; j < BC; j++) {
                float e = __expf(row[j] - mx);
                row[j] = e;
                sum += e;
            }
            float alpha = __expf(mo - mx);
            a_s[t] = alpha;
            m_s[t] = mx;
            l_s[t] = l_s[t] * alpha + sum;
        }
        __syncthreads();

#pragma unroll
        for (int i = 0; i < 4; i++) {
            float al = a_s[ty * 4 + i];
#pragma unroll
            for (int j = 0; j < 8; j++) acc[i][j] *= al;
        }
#pragma unroll 2
        for (int kk = 0; kk < BC; kk++) {
            float4 v0 = *(const float4*)(Vs + kk * VSP + tx * 8);
            float4 v1 = *(const float4*)(Vs + kk * VSP + tx * 8 + 4);
#pragma unroll
            for (int i = 0; i < 4; i++) {
                float p = Ss[(ty * 4 + i) * SSP + kk];
                acc[i][0] += p * v0.x; acc[i][1] += p * v0.y;
                acc[i][2] += p * v0.z; acc[i][3] += p * v0.w;
                acc[i][4] += p * v1.x; acc[i][5] += p * v1.y;
                acc[i][6] += p * v1.z; acc[i][7] += p * v1.w;
            }
        }
    }

#pragma unroll
    for (int i = 0; i < 4; i++) {
        int r = ty * 4 + i;
        float inv = 1.0f / l_s[r];
        float* op = O + (size_t)(q0 + r) * DIM + h * HD + tx * 8;
        *(float4*)op = make_float4(acc[i][0] * inv, acc[i][1] * inv,
                                   acc[i][2] * inv, acc[i][3] * inv);
        *(float4*)(op + 4) = make_float4(acc[i][4] * inv, acc[i][5] * inv,
                                         acc[i][6] * inv, acc[i][7] * inv);
    }
}

// ---------------- launch -------------------------------------------------------
extern "C" void kernel_launch(void* const* d_in, const int* in_sizes, int n_in,
                              void* d_out, int out_size)
{
    const float* x  = (const float*)d_in[0];
    const float* fc = (const float*)d_in[1];
    const float* fs = (const float*)d_in[2];
    const float* wq = (const float*)d_in[3];
    const float* wk = (const float*)d_in[4];
    const float* wv = (const float*)d_in[5];
    const float* wo = (const float*)d_in[6];
    float* out = (float*)d_out;

    float *q, *k, *v, *att;
    cudaGetSymbolAddress((void**)&q,   g_q);
    cudaGetSymbolAddress((void**)&k,   g_k);
    cudaGetSymbolAddress((void**)&v,   g_v);
    cudaGetSymbolAddress((void**)&att, g_att);

    __nv_bfloat16 *xh, *xl, *ath, *atl, *wqh, *wql, *wkh, *wkl, *wvh, *wvl, *woh, *wol;
    cudaGetSymbolAddress((void**)&xh,  g_x_hi);   cudaGetSymbolAddress((void**)&xl,  g_x_lo);
    cudaGetSymbolAddress((void**)&ath, g_att_hi); cudaGetSymbolAddress((void**)&atl, g_att_lo);
    cudaGetSymbolAddress((void**)&wqh, g_wqT_hi); cudaGetSymbolAddress((void**)&wql, g_wqT_lo);
    cudaGetSymbolAddress((void**)&wkh, g_wkT_hi); cudaGetSymbolAddress((void**)&wkl, g_wkT_lo);
    cudaGetSymbolAddress((void**)&wvh, g_wvT_hi); cudaGetSymbolAddress((void**)&wvl, g_wvT_lo);
    cudaGetSymbolAddress((void**)&woh, g_woT_hi); cudaGetSymbolAddress((void**)&wol, g_woT_lo);

    cudaFuncSetAttribute(attn_kernel,
                         cudaFuncAttributeMaxDynamicSharedMemorySize, ATTN_SMEM_BYTES);
    cudaFuncSetAttribute(gemm_mma,
                         cudaFuncAttributeMaxDynamicSharedMemorySize, GEMM_SMEM);

    // split x; transpose+split weights
    split_kernel<<<(SEQ * DIM / 4 + 255) / 256, 256>>>(x, xh, xl, SEQ * DIM / 4);
    tsplit_kernel<<<dim3(DIM / 32, DIM / 32), dim3(32, 8)>>>(wq, wqh, wql, DIM, DIM);
    tsplit_kernel<<<dim3(KVD / 32, DIM / 32), dim3(32, 8)>>>(wk, wkh, wkl, DIM, KVD);
    tsplit_kernel<<<dim3(KVD / 32, DIM / 32), dim3(32, 8)>>>(wv, wvh, wvl, DIM, KVD);
    tsplit_kernel<<<dim3(DIM / 32, DIM / 32), dim3(32, 8)>>>(wo, woh, wol, DIM, DIM);

    // projections on tensor cores (mma.sync)
    gemm_mma<<<dim3(DIM / 128, SEQ / 128), 256, GEMM_SMEM>>>(xh, xl, wqh, wql, q, SEQ, DIM, DIM);
    gemm_mma<<<dim3(KVD / 128, SEQ / 128), 256, GEMM_SMEM>>>(xh, xl, wkh, wkl, k, SEQ, KVD, DIM);
    gemm_mma<<<dim3(KVD / 128, SEQ / 128), 256, GEMM_SMEM>>>(xh, xl, wvh, wvl, v, SEQ, KVD, DIM);

    int nrope = SEQ * (NH + NKV) * (HD / 2);
    rope_kernel<<<(nrope + 255) / 256, 256>>>(q, k, fc, fs);

    attn_kernel<<<dim3(SEQ / BR, NH), 256, ATTN_SMEM_BYTES>>>(q, k, v, att);

    // split attention output, then O-projection
    split_kernel<<<(SEQ * DIM / 4 + 255) / 256, 256>>>(att, ath, atl, SEQ * DIM / 4);
    gemm_mma<<<dim3(DIM / 128, SEQ / 128), 256, GEMM_SMEM>>>(ath, atl, woh, wol, out, SEQ, DIM, DIM);
}

// round 5
// speedup vs baseline: 2.8155x; 1.7264x over previous
#include <cuda_runtime.h>
#include <cuda_bf16.h>
#include <math.h>
#include <stdint.h>

#define SEQ   2048
#define DIM   4096
#define NH    32
#define NKV   8
#define HD    128
#define KVD   1024
#define SCALE 0.08838834764831845f

// ---------------- scratch ----------------------------------------------------
__device__ float g_q[SEQ * DIM];
__device__ float g_k[SEQ * KVD];
__device__ float g_v[SEQ * KVD];

__device__ __nv_bfloat16 g_x_hi[SEQ * DIM],  g_x_lo[SEQ * DIM];
__device__ __nv_bfloat16 g_att_hi[SEQ * DIM], g_att_lo[SEQ * DIM];
__device__ __nv_bfloat16 g_wqT_hi[DIM * DIM], g_wqT_lo[DIM * DIM];
__device__ __nv_bfloat16 g_wkT_hi[KVD * DIM], g_wkT_lo[KVD * DIM];
__device__ __nv_bfloat16 g_wvT_hi[KVD * DIM], g_wvT_lo[KVD * DIM];
__device__ __nv_bfloat16 g_woT_hi[DIM * DIM], g_woT_lo[DIM * DIM];
// bf16 split Q/K/V for attention (Q pre-scaled, RoPE applied)
__device__ __nv_bfloat16 g_qs_hi[SEQ * DIM], g_qs_lo[SEQ * DIM];
__device__ __nv_bfloat16 g_ks_hi[SEQ * KVD], g_ks_lo[SEQ * KVD];
__device__ __nv_bfloat16 g_vs_hi[SEQ * KVD], g_vs_lo[SEQ * KVD];

// ---------------- PTX helpers (baseline PTX only: no tcgen05) -----------------
__device__ __forceinline__ uint32_t smem_u32(const void* p) {
    uint32_t a;
    asm("{ .reg .u64 t; cvta.to.shared.u64 t, %1; cvt.u32.u64 %0, t; }"
        : "=r"(a) : "l"(p));
    return a;
}
#define CP_ASYNC16(dst, src) \
    asm volatile("cp.async.cg.shared.global [%0], [%1], 16;" :: "r"(dst), "l"(src) : "memory")
#define CP_COMMIT()  asm volatile("cp.async.commit_group;" ::: "memory")
#define CP_WAIT(n)   asm volatile("cp.async.wait_group %0;" :: "n"(n) : "memory")

#define LDSM_X4(r, addr)                                                      \
    asm volatile("ldmatrix.sync.aligned.m8n8.x4.shared.b16 {%0,%1,%2,%3}, [%4];" \
        : "=r"((r)[0]), "=r"((r)[1]), "=r"((r)[2]), "=r"((r)[3]) : "r"(addr))
#define LDSM_X4_T(r, addr)                                                    \
    asm volatile("ldmatrix.sync.aligned.m8n8.x4.trans.shared.b16 {%0,%1,%2,%3}, [%4];" \
        : "=r"((r)[0]), "=r"((r)[1]), "=r"((r)[2]), "=r"((r)[3]) : "r"(addr))

#define MMA_BF16(d, a, b0, b1)                                                \
    asm volatile("mma.sync.aligned.m16n8k16.row.col.f32.bf16.bf16.f32 "       \
        "{%0,%1,%2,%3}, {%4,%5,%6,%7}, {%8,%9}, {%0,%1,%2,%3};"               \
        : "+f"((d)[0]), "+f"((d)[1]), "+f"((d)[2]), "+f"((d)[3])              \
        : "r"((a)[0]), "r"((a)[1]), "r"((a)[2]), "r"((a)[3]), "r"(b0), "r"(b1))

__device__ __forceinline__ uint32_t pack_bf16x2(float lo, float hi) {
    __nv_bfloat162 p = __float22bfloat162_rn(make_float2(lo, hi));
    return *(uint32_t*)&p;
}

// ---------------- elementwise split fp32 -> bf16 hi/lo ------------------------
__global__ void split_kernel(const float* __restrict__ in,
                             __nv_bfloat16* __restrict__ hi,
                             __nv_bfloat16* __restrict__ lo, int n4)
{
    int i = blockIdx.x * blockDim.x + threadIdx.x;
    if (i >= n4) return;
    float4 v = ((const float4*)in)[i];
    __nv_bfloat16 h0 = __float2bfloat16(v.x);
    __nv_bfloat16 h1 = __float2bfloat16(v.y);
    __nv_bfloat16 h2 = __float2bfloat16(v.z);
    __nv_bfloat16 h3 = __float2bfloat16(v.w);
    __nv_bfloat16 l0 = __float2bfloat16(v.x - __bfloat162float(h0));
    __nv_bfloat16 l1 = __float2bfloat16(v.y - __bfloat162float(h1));
    __nv_bfloat16 l2 = __float2bfloat16(v.z - __bfloat162float(h2));
    __nv_bfloat16 l3 = __float2bfloat16(v.w - __bfloat162float(h3));
    __nv_bfloat162* hp = (__nv_bfloat162*)hi;
    __nv_bfloat162* lp = (__nv_bfloat162*)lo;
    __nv_bfloat162 a; a.x = h0; a.y = h1; hp[i * 2] = a;
    __nv_bfloat162 b; b.x = h2; b.y = h3; hp[i * 2 + 1] = b;
    __nv_bfloat162 c; c.x = l0; c.y = l1; lp[i * 2] = c;
    __nv_bfloat162 d; d.x = l2; d.y = l3; lp[i * 2 + 1] = d;
}

// ---------------- transpose + split: B[K,N] fp32 -> BT[N,K] bf16 hi/lo --------
__global__ void tsplit_kernel(const float* __restrict__ B,
                              __nv_bfloat16* __restrict__ Th,
                              __nv_bfloat16* __restrict__ Tl, int K, int N)
{
    __shared__ float tile[32][33];
    int n0 = blockIdx.x * 32, k0 = blockIdx.y * 32;
    int tx = threadIdx.x, ty = threadIdx.y;
#pragma unroll
    for (int i = 0; i < 32; i += 8)
        tile[ty + i][tx] = B[(size_t)(k0 + ty + i) * N + n0 + tx];
    __syncthreads();
#pragma unroll
    for (int i = 0; i < 32; i += 8) {
        float v = tile[tx][ty + i];
        __nv_bfloat16 h = __float2bfloat16(v);
        __nv_bfloat16 l = __float2bfloat16(v - __bfloat162float(h));
        size_t o = (size_t)(n0 + ty + i) * K + k0 + tx;
        Th[o] = h;
        Tl[o] = l;
    }
}

// ---------------- mma.sync GEMM (unchanged from R3) ----------------------------
#define BK    32
#define TSTR  40
#define TILE_E (128 * TSTR)
#define GEMM_SMEM (2 * 4 * TILE_E * 2)

__global__ __launch_bounds__(256, 2) void gemm_mma(
    const __nv_bfloat16* __restrict__ Ah, const __nv_bfloat16* __restrict__ Al,
    const __nv_bfloat16* __restrict__ Bh, const __nv_bfloat16* __restrict__ Bl,
    float* __restrict__ C, int M, int N, int K)
{
    extern __shared__ __nv_bfloat16 smb[];
    const uint32_t sbase = smem_u32(smb);
    const int t    = threadIdx.x;
    const int lane = t & 31;
    const int w    = t >> 5;
    const int wm   = w & 1, wn = w >> 1;
    const int m0   = blockIdx.y << 7, n0 = blockIdx.x << 7;

    const __nv_bfloat16* srcs[4] = {
        Ah + (size_t)m0 * K, Al + (size_t)m0 * K,
        Bh + (size_t)n0 * K, Bl + (size_t)n0 * K };

    const int lr = t >> 2, lc = (t & 3) * 8;

    float acc[4][4][4];
#pragma unroll
    for (int a = 0; a < 4; a++)
#pragma unroll
        for (int b = 0; b < 4; b++)
#pragma unroll
            for (int c = 0; c < 4; c++) acc[a][b][c] = 0.f;

#pragma unroll
    for (int tile = 0; tile < 4; tile++) {
        const __nv_bfloat16* s = srcs[tile];
        uint32_t d = sbase + (uint32_t)(tile * TILE_E) * 2;
        CP_ASYNC16(d + (lr * TSTR + lc) * 2,        s + (size_t)lr * K + lc);
        CP_ASYNC16(d + ((lr + 64) * TSTR + lc) * 2, s + (size_t)(lr + 64) * K + lc);
    }
    CP_COMMIT();

    const int niter = K / BK;
    for (int i = 0; i < niter; i++) {
        const int b = i & 1;
        if (i + 1 < niter) {
            const int nb = b ^ 1;
            const size_t koff = (size_t)(i + 1) * BK;
#pragma unroll
            for (int tile = 0; tile < 4; tile++) {
                const __nv_bfloat16* s = srcs[tile] + koff;
                uint32_t d = sbase + (uint32_t)((nb * 4 + tile) * TILE_E) * 2;
                CP_ASYNC16(d + (lr * TSTR + lc) * 2,        s + (size_t)lr * K + lc);
                CP_ASYNC16(d + ((lr + 64) * TSTR + lc) * 2, s + (size_t)(lr + 64) * K + lc);
            }
            CP_COMMIT();
            CP_WAIT(1);
        } else {
            CP_WAIT(0);
        }
        __syncthreads();

        const uint32_t Ah_s = sbase + (uint32_t)((b * 4 + 0) * TILE_E) * 2;
        const uint32_t Al_s = sbase + (uint32_t)((b * 4 + 1) * TILE_E) * 2;
        const uint32_t Bh_s = sbase + (uint32_t)((b * 4 + 2) * TILE_E) * 2;
        const uint32_t Bl_s = sbase + (uint32_t)((b * 4 + 3) * TILE_E) * 2;

#pragma unroll
        for (int ks = 0; ks < 2; ks++) {
            const int koff = ks * 16 + (lane >> 4) * 8;
            const int arow = wm * 64 + (lane & 15);
            const int brow = wn * 32 + (lane & 15);

            uint32_t ah[4][4], al[4][4], bh[2][4], bl[2][4];
#pragma unroll
            for (int mt = 0; mt < 4; mt++) {
                uint32_t off = (uint32_t)((arow + mt * 16) * TSTR + koff) * 2;
                LDSM_X4(ah[mt], Ah_s + off);
                LDSM_X4(al[mt], Al_s + off);
            }
#pragma unroll
            for (int np = 0; np < 2; np++) {
                uint32_t off = (uint32_t)((brow + np * 16) * TSTR + koff) * 2;
                LDSM_X4(bh[np], Bh_s + off);
                LDSM_X4(bl[np], Bl_s + off);
            }
#pragma unroll
            for (int mt = 0; mt < 4; mt++)
#pragma unroll
                for (int nt = 0; nt < 4; nt++) {
                    const int np = nt >> 1, sel = nt & 1;
                    MMA_BF16(acc[mt][nt], ah[mt], bh[np][sel], bh[np][sel + 2]);
                    MMA_BF16(acc[mt][nt], ah[mt], bl[np][sel], bl[np][sel + 2]);
                    MMA_BF16(acc[mt][nt], al[mt], bh[np][sel], bh[np][sel + 2]);
                }
        }
        __syncthreads();
    }

#pragma unroll
    for (int mt = 0; mt < 4; mt++) {
        const int r = m0 + wm * 64 + mt * 16 + (lane >> 2);
#pragma unroll
        for (int nt = 0; nt < 4; nt++) {
            const int c = n0 + wn * 32 + nt * 8 + (lane & 3) * 2;
            *(float2*)(C + (size_t)r * N + c) =
                make_float2(acc[mt][nt][0], acc[mt][nt][1]);
            *(float2*)(C + (size_t)(r + 8) * N + c) =
                make_float2(acc[mt][nt][2], acc[mt][nt][3]);
        }
    }
}

// ---------------- fused RoPE + scale + bf16 split for Q and K -----------------
__global__ void rope_split_kernel(
    const float* __restrict__ q, const float* __restrict__ k,
    const float* __restrict__ fc, const float* __restrict__ fs,
    __nv_bfloat16* __restrict__ qh, __nv_bfloat16* __restrict__ ql,
    __nv_bfloat16* __restrict__ kh, __nv_bfloat16* __restrict__ kl)
{
    int idx = blockIdx.x * blockDim.x + threadIdx.x;
    const int qn = SEQ * NH * (HD / 2);
    const int kn = SEQ * NKV * (HD / 2);
    float o1, o2;
    size_t off;
    __nv_bfloat16 *ph, *pl;
    if (idx < qn) {
        int s = idx / (NH * 64);
        int rem = idx - s * (NH * 64);
        int h = rem >> 6, i = rem & 63;
        float c = fc[s * 64 + i], sn = fs[s * 64 + i];
        off = (size_t)s * DIM + h * HD + 2 * i;
        float t1 = q[off], t2 = q[off + 1];
        o1 = (t1 * c - t2 * sn) * SCALE;
        o2 = (t1 * sn + t2 * c) * SCALE;
        ph = qh; pl = ql;
    } else if (idx < qn + kn) {
        int j = idx - qn;
        int s = j / (NKV * 64);
        int rem = j - s * (NKV * 64);
        int h = rem >> 6, i = rem & 63;
        float c = fc[s * 64 + i], sn = fs[s * 64 + i];
        off = (size_t)s * KVD + h * HD + 2 * i;
        float t1 = k[off], t2 = k[off + 1];
        o1 = t1 * c - t2 * sn;
        o2 = t1 * sn + t2 * c;
        ph = kh; pl = kl;
    } else return;
    __nv_bfloat16 h1 = __float2bfloat16(o1);
    __nv_bfloat16 h2 = __float2bfloat16(o2);
    __nv_bfloat162 hp; hp.x = h1; hp.y = h2;
    __nv_bfloat162 lp;
    lp.x = __float2bfloat16(o1 - __bfloat162float(h1));
    lp.y = __float2bfloat16(o2 - __bfloat162float(h2));
    *(__nv_bfloat162*)(ph + off) = hp;
    *(__nv_bfloat162*)(pl + off) = lp;
}

// ---------------- tensor-core flash attention ---------------------------------
// CTA = (128-q tile, head); 8 warps; warp w owns rows 16w..16w+15.
// BC = 64 KV per iter. bf16x3 split for both QK^T and PV. Softmax in registers.
#define AROWB 272                           // row stride bytes (136 bf16)
#define QT_B  (128 * AROWB)                 // 34816 B per Q tensor
#define KT_B  (64 * AROWB)                  // 17408 B per K/V tensor
#define KVBUF (4 * KT_B)                    // 69632 B per KV buffer
#define ATT_SMEM (2 * QT_B + 2 * KVBUF)     // 208896 B

__global__ __launch_bounds__(256) void attn_tc(
    const __nv_bfloat16* __restrict__ Qh, const __nv_bfloat16* __restrict__ Ql,
    const __nv_bfloat16* __restrict__ Kh, const __nv_bfloat16* __restrict__ Kl,
    const __nv_bfloat16* __restrict__ Vh, const __nv_bfloat16* __restrict__ Vl,
    __nv_bfloat16* __restrict__ Oh, __nv_bfloat16* __restrict__ Ol)
{
    extern __shared__ char smc[];
    const uint32_t sb  = smem_u32(smc);
    const int t = threadIdx.x, lane = t & 31, w = t >> 5;
    const int h = blockIdx.y, q0 = blockIdx.x << 7, kvh = h >> 2;

    const uint32_t sQh = sb;
    const uint32_t sQl = sb + QT_B;
    const uint32_t sKV = sb + 2 * QT_B;   // two buffers of KVBUF

    // ---- prologue: load Q (hi/lo) and KV tile 0 via cp.async ----
    {
        const __nv_bfloat16* qs[2] = { Qh, Ql };
        uint32_t qd[2] = { sQh, sQl };
#pragma unroll
        for (int tn = 0; tn < 2; tn++)
#pragma unroll
            for (int p = 0; p < 8; p++) {
                int chunk = t + p * 256;
                int row = chunk >> 4, c = chunk & 15;
                CP_ASYNC16(qd[tn] + row * AROWB + c * 16,
                           qs[tn] + (size_t)(q0 + row) * DIM + h * HD + c * 8);
            }
    }
    const __nv_bfloat16* kvsrc[4] = { Kh, Kl, Vh, Vl };
#pragma unroll
    for (int tn = 0; tn < 4; tn++)
#pragma unroll
        for (int p = 0; p < 4; p++) {
            int chunk = t + p * 256;
            int row = chunk >> 4, c = chunk & 15;
            CP_ASYNC16(sKV + tn * KT_B + row * AROWB + c * 16,
                       kvsrc[tn] + (size_t)row * KVD + kvh * HD + c * 8);
        }
    CP_COMMIT();

    float m0 = -INFINITY, m1 = -INFINITY, l0 = 0.f, l1 = 0.f;
    float oacc[16][4];
#pragma unroll
    for (int i = 0; i < 16; i++)
#pragma unroll
        for (int j = 0; j < 4; j++) oacc[i][j] = 0.f;

    const int NIT = SEQ / 64;
    for (int it = 0; it < NIT; it++) {
        CP_WAIT(0);
        __syncthreads();
        const uint32_t kvb = sKV + (it & 1) * KVBUF;
        if (it + 1 < NIT) {
            const uint32_t nb = sKV + ((it + 1) & 1) * KVBUF;
            const int k0n = (it + 1) * 64;
#pragma unroll
            for (int tn = 0; tn < 4; tn++)
#pragma unroll
                for (int p = 0; p < 4; p++) {
                    int chunk = t + p * 256;
                    int row = chunk >> 4, c = chunk & 15;
                    CP_ASYNC16(nb + tn * KT_B + row * AROWB + c * 16,
                               kvsrc[tn] + (size_t)(k0n + row) * KVD + kvh * HD + c * 8);
                }
            CP_COMMIT();
        }

        // ---- S = Q K^T  (rows 16w.., 64 cols) ----
        float sacc[8][4];
#pragma unroll
        for (int i = 0; i < 8; i++)
#pragma unroll
            for (int j = 0; j < 4; j++) sacc[i][j] = 0.f;

#pragma unroll
        for (int ks = 0; ks < 8; ks++) {
            const uint32_t aoff = (uint32_t)(16 * w + (lane & 15)) * AROWB
                                + ks * 32 + (lane >> 4) * 16;
            uint32_t ah[4], al[4];
            LDSM_X4(ah, sQh + aoff);
            LDSM_X4(al, sQl + aoff);
#pragma unroll
            for (int g = 0; g < 4; g++) {
                const uint32_t boff = (uint32_t)(g * 16 + (lane & 15)) * AROWB
                                    + ks * 32 + (lane >> 4) * 16;
                uint32_t bh[4], bl[4];
                LDSM_X4(bh, kvb + boff);            // Kh
                LDSM_X4(bl, kvb + KT_B + boff);     // Kl
#pragma unroll
                for (int sel = 0; sel < 2; sel++) {
                    MMA_BF16(sacc[2 * g + sel], ah, bh[sel], bh[sel + 2]);
                    MMA_BF16(sacc[2 * g + sel], ah, bl[sel], bl[sel + 2]);
                    MMA_BF16(sacc[2 * g + sel], al, bh[sel], bh[sel + 2]);
                }
            }
        }

        // ---- online softmax in registers ----
        float mc0 = -INFINITY, mc1 = -INFINITY;
#pragma unroll
        for (int i = 0; i < 8; i++) {
            mc0 = fmaxf(mc0, fmaxf(sacc[i][0], sacc[i][1]));
            mc1 = fmaxf(mc1, fmaxf(sacc[i][2], sacc[i][3]));
        }
        mc0 = fmaxf(mc0, __shfl_xor_sync(0xffffffffu, mc0, 1));
        mc0 = fmaxf(mc0, __shfl_xor_sync(0xffffffffu, mc0, 2));
        mc1 = fmaxf(mc1, __shfl_xor_sync(0xffffffffu, mc1, 1));
        mc1 = fmaxf(mc1, __shfl_xor_sync(0xffffffffu, mc1, 2));
        const float mn0 = fmaxf(m0, mc0), mn1 = fmaxf(m1, mc1);
        const float alpha0 = __expf(m0 - mn0), alpha1 = __expf(m1 - mn1);
        m0 = mn0; m1 = mn1;
        float sum0 = 0.f, sum1 = 0.f;
#pragma unroll
        for (int i = 0; i < 8; i++) {
            sacc[i][0] = __expf(sacc[i][0] - mn0);
            sacc[i][1] = __expf(sacc[i][1] - mn0);
            sacc[i][2] = __expf(sacc[i][2] - mn1);
            sacc[i][3] = __expf(sacc[i][3] - mn1);
            sum0 += sacc[i][0] + sacc[i][1];
            sum1 += sacc[i][2] + sacc[i][3];
        }
        sum0 += __shfl_xor_sync(0xffffffffu, sum0, 1);
        sum0 += __shfl_xor_sync(0xffffffffu, sum0, 2);
        sum1 += __shfl_xor_sync(0xffffffffu, sum1, 1);
        sum1 += __shfl_xor_sync(0xffffffffu, sum1, 2);
        l0 = l0 * alpha0 + sum0;
        l1 = l1 * alpha1 + sum1;

        // rescale O accumulators
#pragma unroll
        for (int i = 0; i < 16; i++) {
            oacc[i][0] *= alpha0; oacc[i][1] *= alpha0;
            oacc[i][2] *= alpha1; oacc[i][3] *= alpha1;
        }

        // ---- P hi/lo fragments (in-register) ----
        // A-frag order for PV chunk ks: a0 = nt0(c0,c1) [r, k_lo], a1 = nt0(c2,c3)
        // [r+8, k_lo], a2 = nt1(c0,c1) [r, k_hi], a3 = nt1(c2,c3) [r+8, k_hi].
        // This is the NATURAL production order — no reordering (R4 bug was a swap here).
        uint32_t pah[4][4], pal[4][4];
#pragma unroll
        for (int ks = 0; ks < 4; ks++) {
#pragma unroll
            for (int half = 0; half < 2; half++) {   // nt = 2ks+half
                const int nt = 2 * ks + half;
                float e0 = sacc[nt][0], e1 = sacc[nt][1];
                float e2 = sacc[nt][2], e3 = sacc[nt][3];
                __nv_bfloat16 h0 = __float2bfloat16(e0);
                __nv_bfloat16 h1 = __float2bfloat16(e1);
                __nv_bfloat16 h2 = __float2bfloat16(e2);
                __nv_bfloat16 h3 = __float2bfloat16(e3);
                pah[ks][2 * half + 0] = pack_bf16x2(e0, e1);
                pah[ks][2 * half + 1] = pack_bf16x2(e2, e3);
                pal[ks][2 * half + 0] = pack_bf16x2(e0 - __bfloat162float(h0),
                                                    e1 - __bfloat162float(h1));
                pal[ks][2 * half + 1] = pack_bf16x2(e2 - __bfloat162float(h2),
                                                    e3 - __bfloat162float(h3));
            }
        }

        // ---- O += P V ----
#pragma unroll
        for (int ks = 0; ks < 4; ks++) {
#pragma unroll
            for (int g = 0; g < 8; g++) {
                const uint32_t voff = (uint32_t)(ks * 16 + (lane & 15)) * AROWB
                                    + (g * 16 + (lane >> 4) * 8) * 2;
                uint32_t vh[4], vl[4];
                LDSM_X4_T(vh, kvb + 2 * KT_B + voff);   // Vh
                LDSM_X4_T(vl, kvb + 3 * KT_B + voff);   // Vl
#pragma unroll
                for (int sel = 0; sel < 2; sel++) {
                    MMA_BF16(oacc[2 * g + sel], pah[ks], vh[2 * sel], vh[2 * sel + 1]);
                    MMA_BF16(oacc[2 * g + sel], pah[ks], vl[2 * sel], vl[2 * sel + 1]);
                    MMA_BF16(oacc[2 * g + sel], pal[ks], vh[2 * sel], vh[2 * sel + 1]);
                }
            }
        }
    }

    // ---- epilogue: O /= l, split to bf16 hi/lo, store ----
    const float inv0 = 1.0f / l0, inv1 = 1.0f / l1;
    const int r0 = q0 + 16 * w + (lane >> 2);
    const int r1 = r0 + 8;
#pragma unroll
    for (int nt = 0; nt < 16; nt++) {
        const int col = h * HD + nt * 8 + (lane & 3) * 2;
        float o0 = oacc[nt][0] * inv0, o1 = oacc[nt][1] * inv0;
        float o2 = oacc[nt][2] * inv1, o3 = oacc[nt][3] * inv1;
        __nv_bfloat16 h0 = __float2bfloat16(o0), h1 = __float2bfloat16(o1);
        __nv_bfloat16 h2 = __float2bfloat16(o2), h3 = __float2bfloat16(o3);
        __nv_bfloat162 hp0; hp0.x = h0; hp0.y = h1;
        __nv_bfloat162 hp1; hp1.x = h2; hp1.y = h3;
        __nv_bfloat162 lp0;
        lp0.x = __float2bfloat16(o0 - __bfloat162float(h0));
        lp0.y = __float2bfloat16(o1 - __bfloat162float(h1));
        __nv_bfloat162 lp1;
        lp1.x = __float2bfloat16(o2 - __bfloat162float(h2));
        lp1.y = __float2bfloat16(o3 - __bfloat162float(h3));
        *(__nv_bfloat162*)(Oh + (size_t)r0 * DIM + col) = hp0;
        *(__nv_bfloat162*)(Oh + (size_t)r1 * DIM + col) = hp1;
        *(__nv_bfloat162*)(Ol + (size_t)r0 * DIM + col) = lp0;
        *(__nv_bfloat162*)(Ol + (size_t)r1 * DIM + col) = lp1;
    }
}

// ---------------- launch -------------------------------------------------------
extern "C" void kernel_launch(void* const* d_in, const int* in_sizes, int n_in,
                              void* d_out, int out_size)
{
    const float* x  = (const float*)d_in[0];
    const float* fc = (const float*)d_in[1];
    const float* fs = (const float*)d_in[2];
    const float* wq = (const float*)d_in[3];
    const float* wk = (const float*)d_in[4];
    const float* wv = (const float*)d_in[5];
    const float* wo = (const float*)d_in[6];
    float* out = (float*)d_out;

    float *q, *k, *v;
    cudaGetSymbolAddress((void**)&q, g_q);
    cudaGetSymbolAddress((void**)&k, g_k);
    cudaGetSymbolAddress((void**)&v, g_v);

    __nv_bfloat16 *xh, *xl, *ath, *atl, *wqh, *wql, *wkh, *wkl, *wvh, *wvl, *woh, *wol;
    __nv_bfloat16 *qsh, *qsl, *ksh, *ksl, *vsh, *vsl;
    cudaGetSymbolAddress((void**)&xh,  g_x_hi);   cudaGetSymbolAddress((void**)&xl,  g_x_lo);
    cudaGetSymbolAddress((void**)&ath, g_att_hi); cudaGetSymbolAddress((void**)&atl, g_att_lo);
    cudaGetSymbolAddress((void**)&wqh, g_wqT_hi); cudaGetSymbolAddress((void**)&wql, g_wqT_lo);
    cudaGetSymbolAddress((void**)&wkh, g_wkT_hi); cudaGetSymbolAddress((void**)&wkl, g_wkT_lo);
    cudaGetSymbolAddress((void**)&wvh, g_wvT_hi); cudaGetSymbolAddress((void**)&wvl, g_wvT_lo);
    cudaGetSymbolAddress((void**)&woh, g_woT_hi); cudaGetSymbolAddress((void**)&wol, g_woT_lo);
    cudaGetSymbolAddress((void**)&qsh, g_qs_hi);  cudaGetSymbolAddress((void**)&qsl, g_qs_lo);
    cudaGetSymbolAddress((void**)&ksh, g_ks_hi);  cudaGetSymbolAddress((void**)&ksl, g_ks_lo);
    cudaGetSymbolAddress((void**)&vsh, g_vs_hi);  cudaGetSymbolAddress((void**)&vsl, g_vs_lo);

    cudaFuncSetAttribute(gemm_mma,
                         cudaFuncAttributeMaxDynamicSharedMemorySize, GEMM_SMEM);
    cudaFuncSetAttribute(attn_tc,
                         cudaFuncAttributeMaxDynamicSharedMemorySize, ATT_SMEM);

    // split x; transpose+split weights
    split_kernel<<<(SEQ * DIM / 4 + 255) / 256, 256>>>(x, xh, xl, SEQ * DIM / 4);
    tsplit_kernel<<<dim3(DIM / 32, DIM / 32), dim3(32, 8)>>>(wq, wqh, wql, DIM, DIM);
    tsplit_kernel<<<dim3(KVD / 32, DIM / 32), dim3(32, 8)>>>(wk, wkh, wkl, DIM, KVD);
    tsplit_kernel<<<dim3(KVD / 32, DIM / 32), dim3(32, 8)>>>(wv, wvh, wvl, DIM, KVD);
    tsplit_kernel<<<dim3(DIM / 32, DIM / 32), dim3(32, 8)>>>(wo, woh, wol, DIM, DIM);

    // projections
    gemm_mma<<<dim3(DIM / 128, SEQ / 128), 256, GEMM_SMEM>>>(xh, xl, wqh, wql, q, SEQ, DIM, DIM);
    gemm_mma<<<dim3(KVD / 128, SEQ / 128), 256, GEMM_SMEM>>>(xh, xl, wkh, wkl, k, SEQ, KVD, DIM);
    gemm_mma<<<dim3(KVD / 128, SEQ / 128), 256, GEMM_SMEM>>>(xh, xl, wvh, wvl, v, SEQ, KVD, DIM);

    // RoPE + scale + split for Q/K; split V
    int nrope = SEQ * (NH + NKV) * (HD / 2);
    rope_split_kernel<<<(nrope + 255) / 256, 256>>>(q, k, fc, fs, qsh, qsl, ksh, ksl);
    split_kernel<<<(SEQ * KVD / 4 + 255) / 256, 256>>>(v, vsh, vsl, SEQ * KVD / 4);

    // tensor-core attention (writes bf16 hi/lo directly)
    attn_tc<<<dim3(SEQ / 128, NH), 256, ATT_SMEM>>>(qsh, qsl, ksh, ksl, vsh, vsl, ath, atl);

    // output projection
    gemm_mma<<<dim3(DIM / 128, SEQ / 128), 256, GEMM_SMEM>>>(ath, atl, woh, wol, out, SEQ, DIM, DIM);
}